// round 3
// baseline (speedup 1.0000x reference)
#include <cuda_runtime.h>
#include <cstdint>

// ---------------------------------------------------------------------------
// x: (B=16, C=256, W=64, P=128) fp32; codebooks: (ns=4, K=256, sc=64) fp32
// idx[s,n] = argmin_k (|c_k|^2 - 2 x_n . c_k),  n = b*8192 + w*128 + p
// out[b, s*64+cc, w, p] = cb[s, idx[s, b*8192 + p*64 + w], cc]
// ---------------------------------------------------------------------------
#define NS 4
#define KCODES 256
#define SC 64
#define NVEC 131072
#define XB_STRIDE 2097152ull
#define CH_STRIDE 8192
#define TILE_M 128
#define NTILES 1024
#define NCHUNKS 148
#define TAU 5e-4f

__device__ int   g_idx[NS * NVEC];
__device__ float g_c2[NS * KCODES];
__device__ int   g_rcnt;
__device__ int   g_rlist[NS * NVEC];

// ---------------------------------------------------------------------------
__device__ __forceinline__ uint32_t tf32_of(float x) {
    uint32_t u;
    asm("cvt.rna.tf32.f32 %0, %1;" : "=r"(u) : "f"(x));
    return u;
}

#define MMA_TF32(d, a0, a1, a2, a3, b0, b1) \
    asm volatile("mma.sync.aligned.m16n8k8.row.col.f32.tf32.tf32.f32 " \
        "{%0,%1,%2,%3}, {%4,%5,%6,%7}, {%8,%9}, {%0,%1,%2,%3};" \
        : "+f"((d)[0]), "+f"((d)[1]), "+f"((d)[2]), "+f"((d)[3]) \
        : "r"(a0), "r"(a1), "r"(a2), "r"(a3), "r"(b0), "r"(b1))

// f32x2 helpers (rescue replicates round-1 arithmetic bit-exactly)
__device__ __forceinline__ unsigned long long pack2(float lo, float hi) {
    unsigned long long r;
    asm("mov.b64 %0, {%1, %2};" : "=l"(r) : "f"(lo), "f"(hi));
    return r;
}
__device__ __forceinline__ unsigned long long ffma2(unsigned long long a,
                                                    unsigned long long b,
                                                    unsigned long long c) {
    unsigned long long d;
    asm("fma.rn.f32x2 %0, %1, %2, %3;" : "=l"(d) : "l"(a), "l"(b), "l"(c));
    return d;
}
__device__ __forceinline__ void unpack2(unsigned long long v, float& lo, float& hi) {
    asm("mov.b64 {%0, %1}, %2;" : "=f"(lo), "=f"(hi) : "l"(v));
}

// ---------------------------------------------------------------------------
// kC2: |c_k|^2 rows + reset rescue counter
// ---------------------------------------------------------------------------
__global__ void kC2(const float* __restrict__ cb) {
    int i = blockIdx.x * 32 + threadIdx.x;      // <<<32,32>>> -> 1024 rows
    if (i == 0) g_rcnt = 0;
    const float4* r = (const float4*)(cb + (size_t)i * SC);
    float acc = 0.0f;
#pragma unroll
    for (int j = 0; j < 16; j++) {
        float4 v = r[j];
        acc = fmaf(v.x, v.x, acc);
        acc = fmaf(v.y, v.y, acc);
        acc = fmaf(v.z, v.z, acc);
        acc = fmaf(v.w, v.w, acc);
    }
    g_c2[i] = acc;
}

// ---------------------------------------------------------------------------
// kArg: persistent split-TF32 mma.sync GEMM + two-smallest epilogue
// grid = 592 (148 chunks x 4 s), block = 256 (8 warps), dyn smem = 218112
// smem: c2s [0,1024) | Bhi [1024) 73728 | Blo [74752) 73728
//       Ahi [148480) 34816 | Alo [183296) 34816
// B row: 72 floats, k-interleaved pairs (k, k+4) adjacent.
// A row (per k): 136 floats, m-interleaved pairs (m, m+8) adjacent per 16-row warp chunk.
// ---------------------------------------------------------------------------
#define OFF_BHI 1024
#define OFF_BLO 74752
#define OFF_AHI 148480
#define OFF_ALO 183296
#define SMEM_MAIN 218112

__global__ __launch_bounds__(256, 1) void kArg(const float* __restrict__ x,
                                               const float* __restrict__ cb) {
    extern __shared__ __align__(16) char sm[];
    float* c2s = (float*)sm;
    char* Bhi = sm + OFF_BHI;
    char* Blo = sm + OFF_BLO;
    char* Ahi = sm + OFF_AHI;
    char* Alo = sm + OFF_ALO;

    const int tid  = threadIdx.x;
    const int w    = tid >> 5;
    const int lane = tid & 31;
    const int g    = lane >> 2;      // groupID (D rows g, g+8 of warp tile)
    const int tg   = lane & 3;       // threadID in group

    const int s = blockIdx.x & 3;
    const int chunk = blockIdx.x >> 2;
    const int ntiles = (NTILES - chunk + NCHUNKS - 1) / NCHUNKS;

    // stage c2 + codebook split (once per CTA)
    c2s[tid] = g_c2[s * KCODES + tid];
    {
        const float* bsrc = cb + (size_t)s * KCODES * SC;
#pragma unroll 4
        for (int e = tid; e < KCODES * SC; e += 256) {
            int n = e >> 6, k = e & 63;
            float v = __ldg(bsrc + e);
            uint32_t hi = tf32_of(v);
            uint32_t lo = tf32_of(v - __uint_as_float(hi));
            uint32_t pos = (uint32_t)((k & ~7) + ((k & 3) << 1) + ((k >> 2) & 1));
            uint32_t off = ((uint32_t)n * 72u + pos) * 4u;
            *(uint32_t*)(Bhi + off) = hi;
            *(uint32_t*)(Blo + off) = lo;
        }
    }

    for (int i = 0; i < ntiles; i++) {
        const int t  = chunk + i * NCHUNKS;
        const int n0 = t * TILE_M;
        const int b  = n0 >> 13;
        const int m0 = n0 & 8191;

        __syncthreads();   // previous tile fully consumed (also orders B stage on i==0)
        // ---- stage A tile (128 rows x 64 ch, hi/lo split) ----
        {
            const float* xp = x + (size_t)b * XB_STRIDE + (size_t)s * SC * CH_STRIDE + m0;
#pragma unroll
            for (int it = 0; it < 32; it++) {
                int e = tid + it * 256;
                int m = e & 127, c = e >> 7;
                float v = __ldg(xp + (size_t)c * CH_STRIDE + m);
                uint32_t hi = tf32_of(v);
                uint32_t lo = tf32_of(v - __uint_as_float(hi));
                uint32_t mp = (uint32_t)((m & 0x70) + ((m & 7) << 1) + ((m >> 3) & 1));
                uint32_t off = ((uint32_t)c * 136u + mp) * 4u;
                *(uint32_t*)(Ahi + off) = hi;
                *(uint32_t*)(Alo + off) = lo;
            }
        }
        __syncthreads();

        // ---- preload A_hi fragments for whole tile (K=64 -> 8 ksteps) ----
        uint32_t af[8][4];
        const char* ahbase = Ahi + (uint32_t)(w * 16 + 2 * g) * 4u;
        const char* albase = Alo + (uint32_t)(w * 16 + 2 * g) * 4u;
#pragma unroll
        for (int ks = 0; ks < 8; ks++) {
            uint2 p0 = *(const uint2*)(ahbase + (uint32_t)(ks * 8 + tg) * 544u);
            uint2 p1 = *(const uint2*)(ahbase + (uint32_t)(ks * 8 + tg + 4) * 544u);
            af[ks][0] = p0.x; af[ks][1] = p0.y; af[ks][2] = p1.x; af[ks][3] = p1.y;
        }

        float b1r0 = 3.4e38f, b2r0 = 3.4e38f, b1r1 = 3.4e38f, b2r1 = 3.4e38f;
        int bir0 = 0, bir1 = 0;

        for (int nc = 0; nc < 4; nc++) {
            float acc[8][4];
#pragma unroll
            for (int u = 0; u < 8; u++) {
                acc[u][0] = 0.f; acc[u][1] = 0.f; acc[u][2] = 0.f; acc[u][3] = 0.f;
            }
            const char* bh = Bhi + ((uint32_t)(nc * 64 + g) * 72u + (uint32_t)tg * 2u) * 4u;
            const char* bl = Blo + ((uint32_t)(nc * 64 + g) * 72u + (uint32_t)tg * 2u) * 4u;

            // pass 0: A_hi * B_hi
#pragma unroll
            for (int ks = 0; ks < 8; ks++) {
#pragma unroll
                for (int sub = 0; sub < 8; sub++) {
                    uint2 bb = *(const uint2*)(bh + sub * 2304 + ks * 32);
                    MMA_TF32(acc[sub], af[ks][0], af[ks][1], af[ks][2], af[ks][3], bb.x, bb.y);
                }
            }
            // pass 1: A_hi * B_lo
#pragma unroll
            for (int ks = 0; ks < 8; ks++) {
#pragma unroll
                for (int sub = 0; sub < 8; sub++) {
                    uint2 bb = *(const uint2*)(bl + sub * 2304 + ks * 32);
                    MMA_TF32(acc[sub], af[ks][0], af[ks][1], af[ks][2], af[ks][3], bb.x, bb.y);
                }
            }
            // pass 2: A_lo * B_hi (A_lo frags loaded inline)
#pragma unroll
            for (int ks = 0; ks < 8; ks++) {
                uint2 p0 = *(const uint2*)(albase + (uint32_t)(ks * 8 + tg) * 544u);
                uint2 p1 = *(const uint2*)(albase + (uint32_t)(ks * 8 + tg + 4) * 544u);
#pragma unroll
                for (int sub = 0; sub < 8; sub++) {
                    uint2 bb = *(const uint2*)(bh + sub * 2304 + ks * 32);
                    MMA_TF32(acc[sub], p0.x, p0.y, p1.x, p1.y, bb.x, bb.y);
                }
            }
            // epilogue: running two-smallest per row (rows g and g+8)
#pragma unroll
            for (int sub = 0; sub < 8; sub++) {
                int kb = nc * 64 + sub * 8 + 2 * tg;
                float2 cc = *(const float2*)(c2s + kb);
                float v00 = fmaf(-2.f, acc[sub][0], cc.x);
                float v01 = fmaf(-2.f, acc[sub][1], cc.y);
                float v10 = fmaf(-2.f, acc[sub][2], cc.x);
                float v11 = fmaf(-2.f, acc[sub][3], cc.y);
                if (v00 < b1r0) { b2r0 = b1r0; b1r0 = v00; bir0 = kb; }
                else if (v00 < b2r0) { b2r0 = v00; }
                if (v01 < b1r0) { b2r0 = b1r0; b1r0 = v01; bir0 = kb + 1; }
                else if (v01 < b2r0) { b2r0 = v01; }
                if (v10 < b1r1) { b2r1 = b1r1; b1r1 = v10; bir1 = kb; }
                else if (v10 < b2r1) { b2r1 = v10; }
                if (v11 < b1r1) { b2r1 = b1r1; b1r1 = v11; bir1 = kb + 1; }
                else if (v11 < b2r1) { b2r1 = v11; }
            }
        }

        // cross-lane merge over the 4-lane quad (xor 1, xor 2 keep g fixed)
#pragma unroll
        for (int d = 1; d <= 2; d <<= 1) {
            float o1 = __shfl_xor_sync(0xFFFFFFFFu, b1r0, d);
            float o2 = __shfl_xor_sync(0xFFFFFFFFu, b2r0, d);
            int   oi = __shfl_xor_sync(0xFFFFFFFFu, bir0, d);
            if (o1 < b1r0 || (o1 == b1r0 && oi < bir0)) {
                b2r0 = fminf(b1r0, o2); b1r0 = o1; bir0 = oi;
            } else b2r0 = fminf(b2r0, o1);
            float p1 = __shfl_xor_sync(0xFFFFFFFFu, b1r1, d);
            float p2 = __shfl_xor_sync(0xFFFFFFFFu, b2r1, d);
            int   pi = __shfl_xor_sync(0xFFFFFFFFu, bir1, d);
            if (p1 < b1r1 || (p1 == b1r1 && pi < bir1)) {
                b2r1 = fminf(b1r1, p2); b1r1 = p1; bir1 = pi;
            } else b2r1 = fminf(b2r1, p1);
        }

        if (tg == 0) {
            int ng = n0 + w * 16 + g;
            g_idx[s * NVEC + ng]     = bir0;
            g_idx[s * NVEC + ng + 8] = bir1;
            if (b2r0 - b1r0 < TAU) {
                int sl = atomicAdd(&g_rcnt, 1);
                g_rlist[sl] = (s << 17) | ng;
            }
            if (b2r1 - b1r1 < TAU) {
                int sl = atomicAdd(&g_rcnt, 1);
                g_rlist[sl] = (s << 17) | (ng + 8);
            }
        }
    }
}

// ---------------------------------------------------------------------------
// kRescue: exact fp32 recompute (bit-identical to round-1 arithmetic)
// ---------------------------------------------------------------------------
__global__ __launch_bounds__(128) void kRescue(const float* __restrict__ x,
                                               const float* __restrict__ cb) {
    int cnt = g_rcnt;
    for (int i = blockIdx.x * blockDim.x + threadIdx.x; i < cnt;
         i += gridDim.x * blockDim.x) {
        int e = g_rlist[i];
        int s = e >> 17, n = e & (NVEC - 1);
        int b = n >> 13, m = n & 8191;
        const float* xp = x + (size_t)b * XB_STRIDE + (size_t)s * SC * CH_STRIDE + m;
        unsigned long long xr[SC / 2];
#pragma unroll
        for (int j = 0; j < SC / 2; j++) {
            float lo = __ldg(xp + (size_t)(2 * j) * CH_STRIDE);
            float hi = __ldg(xp + (size_t)(2 * j + 1) * CH_STRIDE);
            xr[j] = pack2(lo, hi);
        }
        float best = 3.4e38f;
        int bi = 0;
        const float* cbs = cb + (size_t)s * KCODES * SC;
        for (int k = 0; k < KCODES; k++) {
            const ulonglong2* row = (const ulonglong2*)(cbs + (size_t)k * SC);
            unsigned long long a0 = 0ull, a1 = 0ull;
#pragma unroll
            for (int j = 0; j < 16; j++) {
                ulonglong2 v = __ldg(row + j);
                a0 = ffma2(xr[2 * j],     v.x, a0);
                a1 = ffma2(xr[2 * j + 1], v.y, a1);
            }
            float l0, h0, l1, h1;
            unpack2(a0, l0, h0);
            unpack2(a1, l1, h1);
            float dot = (l0 + h0) + (l1 + h1);
            float sc = fmaf(-2.0f, dot, g_c2[s * KCODES + k]);
            if (sc < best) { best = sc; bi = k; }
        }
        g_idx[s * NVEC + n] = bi;
    }
}

// ---------------------------------------------------------------------------
// kB: output gather (unchanged; verified rel_err 0.0 in round 1)
// ---------------------------------------------------------------------------
__global__ __launch_bounds__(256) void kB(const float* __restrict__ cb,
                                          float* __restrict__ out) {
    __shared__ float cbq[KCODES * 17];
    __shared__ int   idxt[64 * 66];

    const int bid  = blockIdx.x;
    const int pblk = bid & 1;
    const int cq   = (bid >> 1) & 3;
    const int b    = (bid >> 3) & 15;
    const int s    = bid >> 7;
    const int t    = threadIdx.x;

    {
        const float4* src = (const float4*)(cb + (size_t)s * KCODES * SC + (size_t)t * SC
                                               + cq * 16);
#pragma unroll
        for (int c4 = 0; c4 < 4; c4++) {
            float4 v = src[c4];
            cbq[t * 17 + c4 * 4 + 0] = v.x;
            cbq[t * 17 + c4 * 4 + 1] = v.y;
            cbq[t * 17 + c4 * 4 + 2] = v.z;
            cbq[t * 17 + c4 * 4 + 3] = v.w;
        }
    }
    {
        const int* src = g_idx + (size_t)s * NVEC + (size_t)b * 8192 + pblk * 4096;
#pragma unroll
        for (int r = 0; r < 16; r++) {
            int i  = r * 256 + t;
            int id = src[i];
            idxt[(i & 63) * 66 + (i >> 6)] = id;
        }
    }
    __syncthreads();

    const int lane = t & 31;
    const int warp = t >> 5;

    for (int w_o = warp; w_o < 64; w_o += 8) {
        int k0 = idxt[w_o * 66 + 2 * lane];
        int k1 = idxt[w_o * 66 + 2 * lane + 1];
        const float* r0 = cbq + k0 * 17;
        const float* r1 = cbq + k1 * 17;
        float* op = out + ((((size_t)b * 256 + s * 64 + cq * 16) * 64 + w_o) * 128)
                        + pblk * 64 + 2 * lane;
#pragma unroll
        for (int c = 0; c < 16; c++) {
            float2 v;
            v.x = r0[c];
            v.y = r1[c];
            *(float2*)(op + (size_t)c * CH_STRIDE) = v;
        }
    }
}

// ---------------------------------------------------------------------------
extern "C" void kernel_launch(void* const* d_in, const int* in_sizes, int n_in,
                              void* d_out, int out_size) {
    const float* x  = (const float*)d_in[0];
    const float* cb = (const float*)d_in[1];
    float* out = (float*)d_out;

    static int configured = 0;
    if (!configured) {
        cudaFuncSetAttribute(kArg, cudaFuncAttributeMaxDynamicSharedMemorySize, SMEM_MAIN);
        configured = 1;
    }

    kC2<<<32, 32>>>(cb);
    kArg<<<NCHUNKS * NS, 256, SMEM_MAIN>>>(x, cb);
    kRescue<<<296, 128>>>(x, cb);
    kB<<<512, 256>>>(cb, out);
}

// round 4
// speedup vs baseline: 1.9611x; 1.9611x over previous
#include <cuda_runtime.h>
#include <cstdint>

// ---------------------------------------------------------------------------
// x: (B=16, C=256, W=64, P=128) fp32; codebooks: (ns=4, K=256, sc=64) fp32
// idx[s,n] = argmin_k (|c_k|^2 - 2 x_n . c_k),  n = b*8192 + w*128 + p
// out[b, s*64+cc, w, p] = cb[s, idx[s, b*8192 + p*64 + w], cc]
// ---------------------------------------------------------------------------
#define NS 4
#define KCODES 256
#define SC 64
#define NVEC 131072
#define XB_STRIDE 2097152ull
#define CH_STRIDE 8192
#define TILE_M 256
#define NTILES_TOT 2048        // 4 s * 512 tiles
#define NCTA 148
#define THR_COEF 4.2e-3f       // > 2 * 2 * (2^-11*2+eps) safety margin

__device__ int   g_idx[NS * NVEC];
__device__ float g_c2[NS * KCODES];
__device__ float g_cmax[NS];
__device__ int   g_rcnt4[NS];
__device__ int   g_rlist4[NS * NVEC];

// ---------------------------------------------------------------------------
__device__ __forceinline__ uint32_t tf32_of(float x) {
    uint32_t u;
    asm("cvt.rna.tf32.f32 %0, %1;" : "=r"(u) : "f"(x));
    return u;
}

#define MMA_TF32(d, a0, a1, a2, a3, b0, b1) \
    asm volatile("mma.sync.aligned.m16n8k8.row.col.f32.tf32.tf32.f32 " \
        "{%0,%1,%2,%3}, {%4,%5,%6,%7}, {%8,%9}, {%0,%1,%2,%3};" \
        : "+f"((d)[0]), "+f"((d)[1]), "+f"((d)[2]), "+f"((d)[3]) \
        : "r"(a0), "r"(a1), "r"(a2), "r"(a3), "r"(b0), "r"(b1))

// f32x2 helpers (rescue replicates round-1 arithmetic exactly)
__device__ __forceinline__ unsigned long long pack2(float lo, float hi) {
    unsigned long long r;
    asm("mov.b64 %0, {%1, %2};" : "=l"(r) : "f"(lo), "f"(hi));
    return r;
}
__device__ __forceinline__ unsigned long long ffma2(unsigned long long a,
                                                    unsigned long long b,
                                                    unsigned long long c) {
    unsigned long long d;
    asm("fma.rn.f32x2 %0, %1, %2, %3;" : "=l"(d) : "l"(a), "l"(b), "l"(c));
    return d;
}
__device__ __forceinline__ void unpack2(unsigned long long v, float& lo, float& hi) {
    asm("mov.b64 {%0, %1}, %2;" : "=f"(lo), "=f"(hi) : "l"(v));
}

// ---------------------------------------------------------------------------
// kC2: per (s,k) |c_k|^2, per-s max row norm, reset rescue counters.
// grid=4 (one block per s), block=256 (one thread per k)
// ---------------------------------------------------------------------------
__global__ void kC2(const float* __restrict__ cb) {
    __shared__ float red[256];
    const int s = blockIdx.x;
    const int k = threadIdx.x;
    if (k < NS) g_rcnt4[k] = 0;   // every block writes same zeros: fine
    const float4* r = (const float4*)(cb + ((size_t)s * KCODES + k) * SC);
    float acc = 0.0f;
#pragma unroll
    for (int j = 0; j < 16; j++) {
        float4 v = r[j];
        acc = fmaf(v.x, v.x, acc);
        acc = fmaf(v.y, v.y, acc);
        acc = fmaf(v.z, v.z, acc);
        acc = fmaf(v.w, v.w, acc);
    }
    g_c2[s * KCODES + k] = acc;
    red[k] = acc;
    __syncthreads();
    for (int st = 128; st > 0; st >>= 1) {
        if (k < st) red[k] = fmaxf(red[k], red[k + st]);
        __syncthreads();
    }
    if (k == 0) g_cmax[s] = sqrtf(red[0]);
}

// ---------------------------------------------------------------------------
// kArg: persistent single-pass TF32 mma.sync + guaranteed-margin epilogue
// grid = 148, block = 512 (16 warps), dyn smem = 143360
// smem: c2s [0,1024) | xn2 [1024,2048) | Bhi [2048, +73728) | Ahi [75776, +67584)
// B row stride 72 floats, pairs (k,k+4) adjacent; A c-stride 264 floats,
// rows pair-interleaved (m, m+8) within each 16-row warp chunk.
// ---------------------------------------------------------------------------
#define OFF_XN2 1024
#define OFF_B   2048
#define OFF_A   75776
#define SMEM_MAIN 143360

__global__ __launch_bounds__(512, 1) void kArg(const float* __restrict__ x,
                                               const float* __restrict__ cb) {
    extern __shared__ __align__(16) char sm[];
    float* c2s = (float*)sm;
    float* xn2 = (float*)(sm + OFF_XN2);
    char*  Bhi = sm + OFF_B;
    char*  Ahi = sm + OFF_A;

    const int tid  = threadIdx.x;
    const int w    = tid >> 5;
    const int lane = tid & 31;
    const int g    = lane >> 2;
    const int tg   = lane & 3;

    int   cur_s = -1;
    float cmax  = 0.0f;

    for (int t = blockIdx.x; t < NTILES_TOT; t += NCTA) {
        const int s    = t >> 9;
        const int tloc = t & 511;
        const int n0   = tloc * TILE_M;
        const int b    = n0 >> 13;
        const int m0   = n0 & 8191;

        if (s != cur_s) {
            __syncthreads();                 // old B fully consumed
            const float* bsrc = cb + (size_t)s * KCODES * SC;
#pragma unroll 4
            for (int e = tid; e < KCODES * SC; e += 512) {
                int n = e >> 6, k = e & 63;
                float v = __ldg(bsrc + e);
                uint32_t pos = (uint32_t)((k & ~7) + ((k & 3) << 1) + ((k >> 2) & 1));
                *(uint32_t*)(Bhi + ((uint32_t)n * 72u + pos) * 4u) = tf32_of(v);
            }
            if (tid < KCODES) c2s[tid] = g_c2[s * KCODES + tid];
            cmax = __ldg(&g_cmax[s]);
            cur_s = s;
        }

        __syncthreads();                     // old A fully consumed
        // ---- stage A (256 rows x 64 ch): thread pair (tid, tid^1) per row ----
        {
            const int m    = tid >> 1;
            const int half = tid & 1;
            const float* xp = x + (size_t)b * XB_STRIDE + (size_t)s * SC * CH_STRIDE
                            + m0 + m;
            const uint32_t mp = (uint32_t)((m & 0xF0) + ((m & 7) << 1) + ((m >> 3) & 1));
            float nrm = 0.0f;
#pragma unroll 8
            for (int j = 0; j < 32; j++) {
                int c = half * 32 + j;
                float v = __ldg(xp + (size_t)c * CH_STRIDE);
                nrm = fmaf(v, v, nrm);
                *(uint32_t*)(Ahi + ((uint32_t)c * 264u + mp) * 4u) = tf32_of(v);
            }
            float o = __shfl_xor_sync(0xFFFFFFFFu, nrm, 1);
            if (!half) xn2[m] = nrm + o;
        }
        __syncthreads();

        const char* abase = Ahi + (uint32_t)(w * 16 + 2 * g) * 4u;
        float b1r0 = 3.4e38f, b2r0 = 3.4e38f, b1r1 = 3.4e38f, b2r1 = 3.4e38f;
        int bir0 = 0, bir1 = 0;

        for (int nc = 0; nc < 4; nc++) {
            float acc[8][4];
#pragma unroll
            for (int u = 0; u < 8; u++) {
                acc[u][0] = 0.f; acc[u][1] = 0.f; acc[u][2] = 0.f; acc[u][3] = 0.f;
            }
            const char* bh = Bhi + ((uint32_t)(nc * 64 + g) * 72u + (uint32_t)tg * 2u) * 4u;
#pragma unroll
            for (int ks = 0; ks < 8; ks++) {
                uint2 p0 = *(const uint2*)(abase + (uint32_t)(ks * 8 + tg) * 1056u);
                uint2 p1 = *(const uint2*)(abase + (uint32_t)(ks * 8 + tg + 4) * 1056u);
#pragma unroll
                for (int sub = 0; sub < 8; sub++) {
                    uint2 bb = *(const uint2*)(bh + sub * 2304 + ks * 32);
                    MMA_TF32(acc[sub], p0.x, p0.y, p1.x, p1.y, bb.x, bb.y);
                }
            }
#pragma unroll
            for (int sub = 0; sub < 8; sub++) {
                int kb = nc * 64 + sub * 8 + 2 * tg;
                float2 cc = *(const float2*)(c2s + kb);
                float v00 = fmaf(-2.f, acc[sub][0], cc.x);
                float v01 = fmaf(-2.f, acc[sub][1], cc.y);
                float v10 = fmaf(-2.f, acc[sub][2], cc.x);
                float v11 = fmaf(-2.f, acc[sub][3], cc.y);
                if (v00 < b1r0) { b2r0 = b1r0; b1r0 = v00; bir0 = kb; }
                else if (v00 < b2r0) { b2r0 = v00; }
                if (v01 < b1r0) { b2r0 = b1r0; b1r0 = v01; bir0 = kb + 1; }
                else if (v01 < b2r0) { b2r0 = v01; }
                if (v10 < b1r1) { b2r1 = b1r1; b1r1 = v10; bir1 = kb; }
                else if (v10 < b2r1) { b2r1 = v10; }
                if (v11 < b1r1) { b2r1 = b1r1; b1r1 = v11; bir1 = kb + 1; }
                else if (v11 < b2r1) { b2r1 = v11; }
            }
        }

        // merge two-smallest across the 4-lane quad
#pragma unroll
        for (int d = 1; d <= 2; d <<= 1) {
            float o1 = __shfl_xor_sync(0xFFFFFFFFu, b1r0, d);
            float o2 = __shfl_xor_sync(0xFFFFFFFFu, b2r0, d);
            int   oi = __shfl_xor_sync(0xFFFFFFFFu, bir0, d);
            if (o1 < b1r0 || (o1 == b1r0 && oi < bir0)) {
                b2r0 = fminf(b1r0, o2); b1r0 = o1; bir0 = oi;
            } else b2r0 = fminf(b2r0, o1);
            float p1 = __shfl_xor_sync(0xFFFFFFFFu, b1r1, d);
            float p2 = __shfl_xor_sync(0xFFFFFFFFu, b2r1, d);
            int   pi = __shfl_xor_sync(0xFFFFFFFFu, bir1, d);
            if (p1 < b1r1 || (p1 == b1r1 && pi < bir1)) {
                b2r1 = fminf(b1r1, p2); b1r1 = p1; bir1 = pi;
            } else b2r1 = fminf(b2r1, p1);
        }

        if (tg == 0) {
            int r0 = w * 16 + g;
            int ng = n0 + r0;
            g_idx[s * NVEC + ng]     = bir0;
            g_idx[s * NVEC + ng + 8] = bir1;
            float thr0 = THR_COEF * sqrtf(xn2[r0])     * cmax;
            float thr1 = THR_COEF * sqrtf(xn2[r0 + 8]) * cmax;
            if (b2r0 - b1r0 < thr0) {
                int sl = atomicAdd(&g_rcnt4[s], 1);
                g_rlist4[s * NVEC + sl] = ng;
            }
            if (b2r1 - b1r1 < thr1) {
                int sl = atomicAdd(&g_rcnt4[s], 1);
                g_rlist4[s * NVEC + sl] = ng + 8;
            }
        }
    }
}

// ---------------------------------------------------------------------------
// kRescue: exact fp32 full rescan of flagged vectors, codebook in smem.
// grid = 128 (32 blocks per s), block = 256, dyn smem = 66560
// ---------------------------------------------------------------------------
#define SMEM_RESC 66560

__global__ __launch_bounds__(256) void kRescue(const float* __restrict__ x,
                                               const float* __restrict__ cb) {
    extern __shared__ __align__(16) char smr[];
    float* c2S = (float*)smr;                 // 1 KB
    float* cbS = (float*)(smr + 1024);        // 64 KB

    const int sb  = blockIdx.x & 3;
    const int blk = blockIdx.x >> 2;          // 0..31
    const int tid = threadIdx.x;

    for (int e = tid; e < KCODES * SC; e += 256)
        cbS[e] = __ldg(cb + (size_t)sb * KCODES * SC + e);
    if (tid < KCODES) c2S[tid] = g_c2[sb * KCODES + tid];
    __syncthreads();

    const int cnt = g_rcnt4[sb];
    for (int i = blk * 256 + tid; i < cnt; i += 32 * 256) {
        const int n = g_rlist4[sb * NVEC + i];
        const int b = n >> 13, m = n & 8191;
        const float* xp = x + (size_t)b * XB_STRIDE + (size_t)sb * SC * CH_STRIDE + m;
        unsigned long long xr[SC / 2];
#pragma unroll
        for (int j = 0; j < SC / 2; j++) {
            float lo = __ldg(xp + (size_t)(2 * j) * CH_STRIDE);
            float hi = __ldg(xp + (size_t)(2 * j + 1) * CH_STRIDE);
            xr[j] = pack2(lo, hi);
        }
        float best = 3.4e38f;
        int bi = 0;
        for (int k = 0; k < KCODES; k++) {
            const ulonglong2* row = (const ulonglong2*)(cbS + (size_t)k * SC);
            unsigned long long a0 = 0ull, a1 = 0ull;
#pragma unroll
            for (int j = 0; j < 16; j++) {
                ulonglong2 v = row[j];
                a0 = ffma2(xr[2 * j],     v.x, a0);
                a1 = ffma2(xr[2 * j + 1], v.y, a1);
            }
            float l0, h0, l1, h1;
            unpack2(a0, l0, h0);
            unpack2(a1, l1, h1);
            float dot = (l0 + h0) + (l1 + h1);
            float sc = fmaf(-2.0f, dot, c2S[k]);
            if (sc < best) { best = sc; bi = k; }
        }
        g_idx[sb * NVEC + n] = bi;
    }
}

// ---------------------------------------------------------------------------
// kB: output gather (verified rel_err 0.0)
// ---------------------------------------------------------------------------
__global__ __launch_bounds__(256) void kB(const float* __restrict__ cb,
                                          float* __restrict__ out) {
    __shared__ float cbq[KCODES * 17];
    __shared__ int   idxt[64 * 66];

    const int bid  = blockIdx.x;
    const int pblk = bid & 1;
    const int cq   = (bid >> 1) & 3;
    const int b    = (bid >> 3) & 15;
    const int s    = bid >> 7;
    const int t    = threadIdx.x;

    {
        const float4* src = (const float4*)(cb + (size_t)s * KCODES * SC + (size_t)t * SC
                                               + cq * 16);
#pragma unroll
        for (int c4 = 0; c4 < 4; c4++) {
            float4 v = src[c4];
            cbq[t * 17 + c4 * 4 + 0] = v.x;
            cbq[t * 17 + c4 * 4 + 1] = v.y;
            cbq[t * 17 + c4 * 4 + 2] = v.z;
            cbq[t * 17 + c4 * 4 + 3] = v.w;
        }
    }
    {
        const int* src = g_idx + (size_t)s * NVEC + (size_t)b * 8192 + pblk * 4096;
#pragma unroll
        for (int r = 0; r < 16; r++) {
            int i  = r * 256 + t;
            int id = src[i];
            idxt[(i & 63) * 66 + (i >> 6)] = id;
        }
    }
    __syncthreads();

    const int lane = t & 31;
    const int warp = t >> 5;

    for (int w_o = warp; w_o < 64; w_o += 8) {
        int k0 = idxt[w_o * 66 + 2 * lane];
        int k1 = idxt[w_o * 66 + 2 * lane + 1];
        const float* r0 = cbq + k0 * 17;
        const float* r1 = cbq + k1 * 17;
        float* op = out + ((((size_t)b * 256 + s * 64 + cq * 16) * 64 + w_o) * 128)
                        + pblk * 64 + 2 * lane;
#pragma unroll
        for (int c = 0; c < 16; c++) {
            float2 v;
            v.x = r0[c];
            v.y = r1[c];
            *(float2*)(op + (size_t)c * CH_STRIDE) = v;
        }
    }
}

// ---------------------------------------------------------------------------
extern "C" void kernel_launch(void* const* d_in, const int* in_sizes, int n_in,
                              void* d_out, int out_size) {
    const float* x  = (const float*)d_in[0];
    const float* cb = (const float*)d_in[1];
    float* out = (float*)d_out;

    static int configured = 0;
    if (!configured) {
        cudaFuncSetAttribute(kArg, cudaFuncAttributeMaxDynamicSharedMemorySize, SMEM_MAIN);
        cudaFuncSetAttribute(kRescue, cudaFuncAttributeMaxDynamicSharedMemorySize, SMEM_RESC);
        configured = 1;
    }

    kC2<<<4, 256>>>(cb);
    kArg<<<NCTA, 512, SMEM_MAIN>>>(x, cb);
    kRescue<<<128, 256, SMEM_RESC>>>(x, cb);
    kB<<<512, 256>>>(cb, out);
}